// round 6
// baseline (speedup 1.0000x reference)
#include <cuda_runtime.h>
#include <cuda_fp16.h>
#include <cstdint>

// ===========================================================================
// BitNetSummaryEncoder — HMMA, register-resident W (hi+lo), single-fp16 A,
// double-buffered A with phase-mixed pipeline.
//   Warp w owns output cols [16w,16w+16) (h and g) for ALL 512 rows/tile.
//   2-term split:  A_fp16 * Whi + A_fp16 * Wlo   (W error ~2^-22, A ~2^-12)
//   z = h * sigmoid(g); LN via cross-warp smem reduce + L2-hot pass2.
// ===========================================================================

#define THREADS       512
#define ROWS_PER_CTA  512
#define MTILES        32

__device__ float d_q[848];    // quantized ternary weights

// ---------------- smem layout (bytes) --------------------------------------
// init:   [0,65536) W hi   [65536,131072) W lo
// main:   [0,65536) A buf0 [65536,131072) A buf1   (W region reused)
#define SM_WH   0u
#define SM_WL   65536u
#define SM_RED  131072u       // 512 rows x 17 float2 = 69632
#define SM_STAT 200704u       // 512 x float2 = 4096
#define SM_PAR  204800u       // params (float offsets below)
#define P_CEMB  0
#define P_REMB  320
#define P_Q     640
#define P_SB    1488
#define P_LNG   1552
#define P_LNB   1808
#define P_END   2064
#define SMEM_BYTES (SM_PAR + P_END * 4)   // 213056

// ---------------- PTX helpers -----------------------------------------------
__device__ __forceinline__ uint32_t smem_u32(const void* p) {
    uint32_t a;
    asm("{ .reg .u64 t; cvta.to.shared.u64 t, %1; cvt.u32.u64 %0, t; }"
        : "=r"(a) : "l"(p));
    return a;
}
__device__ __forceinline__ void ldsm_x4(uint32_t* r, uint32_t addr) {
    asm volatile("ldmatrix.sync.aligned.m8n8.x4.shared.b16 {%0,%1,%2,%3}, [%4];"
                 : "=r"(r[0]), "=r"(r[1]), "=r"(r[2]), "=r"(r[3]) : "r"(addr));
}
__device__ __forceinline__ void ldsm_x4t(uint32_t* r, uint32_t addr) {
    asm volatile("ldmatrix.sync.aligned.m8n8.x4.trans.shared.b16 {%0,%1,%2,%3}, [%4];"
                 : "=r"(r[0]), "=r"(r[1]), "=r"(r[2]), "=r"(r[3]) : "r"(addr));
}
__device__ __forceinline__ void mma16816(float* d, const uint32_t* a,
                                         const uint32_t* b) {
    asm volatile(
        "mma.sync.aligned.m16n8k16.row.col.f32.f16.f16.f32 "
        "{%0,%1,%2,%3}, {%4,%5,%6,%7}, {%8,%9}, {%0,%1,%2,%3};"
        : "+f"(d[0]), "+f"(d[1]), "+f"(d[2]), "+f"(d[3])
        : "r"(a[0]), "r"(a[1]), "r"(a[2]), "r"(a[3]), "r"(b[0]), "r"(b[1]));
}
__device__ __forceinline__ float gelu_exact(float x) {
    return 0.5f * x * (1.0f + erff(x * 0.7071067811865476f));
}
__device__ __forceinline__ uint32_t pack2h(float a, float b) {
    __half h0 = __float2half_rn(a);
    __half h1 = __float2half_rn(b);
    return (uint32_t)__half_as_ushort(h0) | ((uint32_t)__half_as_ushort(h1) << 16);
}

// ---------------------------------------------------------------------------
__global__ void quant_prep_kernel(const float* __restrict__ vw1,
                                  const float* __restrict__ vw2,
                                  const float* __restrict__ pw1,
                                  const float* __restrict__ pw2) {
    __shared__ float red[512];
    const float* W; int n; float* out;
    switch (blockIdx.x) {
        case 0:  W = vw1; n = 32;  out = d_q;       break;
        case 1:  W = vw2; n = 48;  out = d_q + 32;  break;
        case 2:  W = pw1; n = 288; out = d_q + 80;  break;
        default: W = pw2; n = 480; out = d_q + 368; break;
    }
    int t = threadIdx.x;
    red[t] = (t < n) ? fabsf(W[t]) : 0.0f;
    __syncthreads();
#pragma unroll
    for (int s = 256; s > 0; s >>= 1) {
        if (t < s) red[t] += red[t + s];
        __syncthreads();
    }
    float scale = red[0] / (float)n;
    if (t < n) {
        float q = rintf(W[t] / (scale + 1e-5f));
        q = fminf(fmaxf(q, -1.0f), 1.0f);
        out[t] = q * scale;
    }
}

// ---------------------------------------------------------------------------
__global__ void __launch_bounds__(THREADS, 1)
encoder_hmma_kernel(const int* __restrict__ read_count,
                    const int* __restrict__ write_count,
                    const int* __restrict__ fault_count,
                    const int* __restrict__ cow_count,
                    const int* __restrict__ recency,
                    const float* __restrict__ volatility,
                    const float* __restrict__ pressure,
                    const float* __restrict__ count_emb,
                    const float* __restrict__ recency_emb,
                    const float* __restrict__ p_b1,
                    const float* __restrict__ p_b2,
                    const float* __restrict__ v_b1,
                    const float* __restrict__ v_b2,
                    const float* __restrict__ f_wh,
                    const float* __restrict__ f_bh,
                    const float* __restrict__ f_wg,
                    const float* __restrict__ f_bg,
                    const float* __restrict__ ln_g,
                    const float* __restrict__ ln_b,
                    float* __restrict__ out,
                    int num_tiles) {
    extern __shared__ char smraw[];
    float* spar = (float*)(smraw + SM_PAR);
    const uint32_t sbase = smem_u32(smraw);
    const int tid = threadIdx.x;
    const int w   = tid >> 5;
    const int lid = tid & 31;

    // ---- build W hi/lo in smem (k-major, 1024B rows, 16B-chunk swizzle) ----
    for (int i = tid; i < 512 * 64; i += THREADS) {
        int n = i >> 6, k = i & 63;
        float wv = 0.0f;
        if (k < 51)       wv = (n < 256) ? f_wh[n * 51 + k] : f_wg[(n - 256) * 51 + k];
        else if (k == 51) wv = (n < 256) ? f_bh[n] : f_bg[n - 256];
        __half hi = __float2half_rn(wv);
        __half lo = __float2half_rn(wv - __half2float(hi));
        uint32_t off = (uint32_t)k * 1024u + ((((uint32_t)n >> 3) ^ ((uint32_t)k & 7)) << 4)
                       + (((uint32_t)n & 7) << 1);
        *(__half*)(smraw + SM_WH + off) = hi;
        *(__half*)(smraw + SM_WL + off) = lo;
    }
    for (int i = tid; i < 320; i += THREADS) {
        spar[P_CEMB + i] = count_emb[i];
        spar[P_REMB + i] = recency_emb[i];
    }
    for (int i = tid; i < 848; i += THREADS) spar[P_Q + i] = d_q[i];
    if (tid < 8)  spar[P_SB + tid]      = v_b1[tid];
    if (tid < 6)  spar[P_SB + 8 + tid]  = v_b2[tid];
    if (tid < 24) spar[P_SB + 16 + tid] = p_b1[tid];
    if (tid < 20) spar[P_SB + 40 + tid] = p_b2[tid];
    if (tid < 256) { spar[P_LNG + tid] = ln_g[tid]; spar[P_LNB + tid] = ln_b[tid]; }
    __syncthreads();

    const float* s_q  = spar + P_Q;
    const float* s_sb = spar + P_SB;
    float2* red2  = (float2*)(smraw + SM_RED);
    float2* stat2 = (float2*)(smraw + SM_STAT);

    const int grp = lid >> 3, li = lid & 7;
    const int r0  = lid >> 2;           // 0..7
    const int cql = (lid & 3) << 1;     // 0,2,4,6

    // ---- register-resident W fragments (once): hi and lo terms -------------
    // c 0..1: h chunks (cols 16w..16w+16); c 2..3: g chunks (+256)
    uint32_t Bhi[4][8], Blo[4][8];
#pragma unroll
    for (int c = 0; c < 2; c++) {
        const int chh = w * 2 + c;
        const int chg = 32 + w * 2 + c;
#pragma unroll
        for (int kh = 0; kh < 2; kh++) {
            int krow = kh * 32 + grp * 8 + li;
            uint32_t rowoff = (uint32_t)krow * 1024u;
            uint32_t swh = (((uint32_t)(chh ^ (krow & 7))) << 4);
            uint32_t swg = (((uint32_t)(chg ^ (krow & 7))) << 4);
            ldsm_x4t(&Bhi[c][kh * 4],     sbase + SM_WH + rowoff + swh);
            ldsm_x4t(&Blo[c][kh * 4],     sbase + SM_WL + rowoff + swh);
            ldsm_x4t(&Bhi[2 + c][kh * 4], sbase + SM_WH + rowoff + swg);
            ldsm_x4t(&Blo[2 + c][kh * 4], sbase + SM_WL + rowoff + swg);
        }
    }
    __syncthreads();   // W frags in regs; W smem region now reusable as A bufs

    // ---- phase0: scalar front-end, one row/thread -> A[buf] ----------------
    auto phase0 = [&](int tile, int buf) {
        const size_t myrow = (size_t)tile * ROWS_PER_CTA + tid;
        const uint32_t abase = (uint32_t)buf * 65536u + (uint32_t)tid * 128u;
        float v8[8];
        auto store_chunk = [&](int j, const float* v) {
            uint32_t hw[4];
#pragma unroll
            for (int q = 0; q < 4; q++) hw[q] = pack2h(v[2 * q], v[2 * q + 1]);
            uint32_t off = abase + (((uint32_t)(j ^ (tid & 7))) << 4);
            *(uint4*)(smraw + off) = make_uint4(hw[0], hw[1], hw[2], hw[3]);
        };
        const int rc = read_count[myrow], wc = write_count[myrow];
        const int fc = fault_count[myrow], cc = cow_count[myrow];
        const int rr = recency[myrow];
        // chunk 0: cemb[rc][0..4], cemb[wc][0..2]
#pragma unroll
        for (int d = 0; d < 5; d++) v8[d] = spar[P_CEMB + rc * 5 + d];
#pragma unroll
        for (int d = 0; d < 3; d++) v8[5 + d] = spar[P_CEMB + wc * 5 + d];
        store_chunk(0, v8);
        // chunk 1: cemb[wc][3,4], cemb[fc][0..4], cemb[cc][0]
        v8[0] = spar[P_CEMB + wc * 5 + 3];
        v8[1] = spar[P_CEMB + wc * 5 + 4];
#pragma unroll
        for (int d = 0; d < 5; d++) v8[2 + d] = spar[P_CEMB + fc * 5 + d];
        v8[7] = spar[P_CEMB + cc * 5 + 0];
        store_chunk(1, v8);
        // chunk 2: cemb[cc][1..4], remb[rr][0..3]
#pragma unroll
        for (int d = 0; d < 4; d++) v8[d] = spar[P_CEMB + cc * 5 + 1 + d];
#pragma unroll
        for (int d = 0; d < 4; d++) v8[4 + d] = spar[P_REMB + rr * 5 + d];
        store_chunk(2, v8);

        float4 v4 = ((const float4*)volatility)[myrow];
        float va[4] = {v4.x, v4.y, v4.z, v4.w};
        float v1[8];
#pragma unroll
        for (int j = 0; j < 8; j++) {
            float a = s_sb[j];
#pragma unroll
            for (int i = 0; i < 4; i++) a = fmaf(s_q[j * 4 + i], va[i], a);
            v1[j] = gelu_exact(a);
        }
        float pv[6];
#pragma unroll
        for (int j = 0; j < 6; j++) {
            float a = s_sb[8 + j];
#pragma unroll
            for (int i = 0; i < 8; i++) a = fmaf(s_q[32 + j * 8 + i], v1[i], a);
            pv[j] = a;
        }
        float4 pA = ((const float4*)pressure)[myrow * 3 + 0];
        float4 pB = ((const float4*)pressure)[myrow * 3 + 1];
        float4 pC = ((const float4*)pressure)[myrow * 3 + 2];
        float pr[12] = {pA.x, pA.y, pA.z, pA.w, pB.x, pB.y, pB.z, pB.w,
                        pC.x, pC.y, pC.z, pC.w};
        float p1[24];
#pragma unroll
        for (int j = 0; j < 24; j++) {
            float a = s_sb[16 + j];
#pragma unroll
            for (int i = 0; i < 12; i++) a = fmaf(s_q[80 + j * 12 + i], pr[i], a);
            p1[j] = gelu_exact(a);
        }
        auto pp = [&](int j) {
            float a = s_sb[40 + j];
#pragma unroll
            for (int i = 0; i < 24; i++) a = fmaf(s_q[368 + j * 24 + i], p1[i], a);
            return a;
        };
        // chunk 3: remb[rr][4], pv[0..5], pp(0)
        v8[0] = spar[P_REMB + rr * 5 + 4];
#pragma unroll
        for (int d = 0; d < 6; d++) v8[1 + d] = pv[d];
        v8[7] = pp(0);
        store_chunk(3, v8);
#pragma unroll
        for (int d = 0; d < 8; d++) v8[d] = pp(1 + d);
        store_chunk(4, v8);
#pragma unroll
        for (int d = 0; d < 8; d++) v8[d] = pp(9 + d);
        store_chunk(5, v8);
        v8[0] = pp(17); v8[1] = pp(18); v8[2] = pp(19);
        v8[3] = 1.0f; v8[4] = 0.f; v8[5] = 0.f; v8[6] = 0.f; v8[7] = 0.f;
        store_chunk(6, v8);
#pragma unroll
        for (int d = 0; d < 8; d++) v8[d] = 0.f;
        store_chunk(7, v8);
    };

    // ---- GEMM + epilogue pass 1 --------------------------------------------
    auto gemm_epi = [&](int tile, int buf) {
        const size_t rowbase = (size_t)tile * ROWS_PER_CTA;
        const uint32_t abase = sbase + (uint32_t)buf * 65536u;
#pragma unroll 1
        for (int mt = 0; mt < MTILES; mt++) {
            float acc[4][4];
#pragma unroll
            for (int c = 0; c < 4; c++)
#pragma unroll
                for (int i = 0; i < 4; i++) acc[c][i] = 0.0f;

            const int rloc = mt * 16 + ((grp & 1) << 3) + li;
            const uint32_t roff = (uint32_t)rloc * 128u;
#pragma unroll
            for (int ks = 0; ks < 4; ks++) {
                uint32_t A[4];
                const int ch = 2 * ks + (grp >> 1);
                const uint32_t off = roff + (((uint32_t)(ch ^ (rloc & 7))) << 4);
                ldsm_x4(A, abase + off);
#pragma unroll
                for (int c = 0; c < 4; c++) {
                    mma16816(acc[c], A, &Bhi[c][2 * ks]);
                    mma16816(acc[c], A, &Blo[c][2 * ks]);
                }
            }
            float s0 = 0.f, q0 = 0.f, s8 = 0.f, q8 = 0.f;
            const size_t ra = rowbase + (size_t)(mt * 16 + r0);
#pragma unroll
            for (int c = 0; c < 2; c++) {
                float z0 = acc[c][0] / (1.0f + __expf(-acc[2 + c][0]));
                float z1 = acc[c][1] / (1.0f + __expf(-acc[2 + c][1]));
                float z2 = acc[c][2] / (1.0f + __expf(-acc[2 + c][2]));
                float z3 = acc[c][3] / (1.0f + __expf(-acc[2 + c][3]));
                const int col = w * 16 + c * 8 + cql;
                *(float2*)(out + ra * 256 + col)       = make_float2(z0, z1);
                *(float2*)(out + (ra + 8) * 256 + col) = make_float2(z2, z3);
                s0 += z0 + z1;
                q0 = fmaf(z0, z0, fmaf(z1, z1, q0));
                s8 += z2 + z3;
                q8 = fmaf(z2, z2, fmaf(z3, z3, q8));
            }
            s0 += __shfl_xor_sync(0xffffffffu, s0, 1);
            q0 += __shfl_xor_sync(0xffffffffu, q0, 1);
            s8 += __shfl_xor_sync(0xffffffffu, s8, 1);
            q8 += __shfl_xor_sync(0xffffffffu, q8, 1);
            s0 += __shfl_xor_sync(0xffffffffu, s0, 2);
            q0 += __shfl_xor_sync(0xffffffffu, q0, 2);
            s8 += __shfl_xor_sync(0xffffffffu, s8, 2);
            q8 += __shfl_xor_sync(0xffffffffu, q8, 2);
            if ((lid & 3) == 0) {
                red2[(mt * 16 + r0) * 17 + w]     = make_float2(s0, q0);
                red2[(mt * 16 + 8 + r0) * 17 + w] = make_float2(s8, q8);
            }
        }
    };

    // ---- pass 2: normalize (L2-hot) ----------------------------------------
    auto pass2 = [&](int tile) {
        const float4* lng4 = (const float4*)(spar + P_LNG);
        const float4* lnb4 = (const float4*)(spar + P_LNB);
        float4* out4 = (float4*)(out + (size_t)tile * ROWS_PER_CTA * 256);
#pragma unroll 4
        for (int i = tid; i < ROWS_PER_CTA * 64; i += THREADS) {
            const int r = i >> 6, c4 = i & 63;
            float4 z = out4[i];
            float2 st = stat2[r];
            float4 gg = lng4[c4];
            float4 bb = lnb4[c4];
            z.x = fmaf((z.x - st.x) * st.y, gg.x, bb.x);
            z.y = fmaf((z.y - st.x) * st.y, gg.y, bb.y);
            z.z = fmaf((z.z - st.x) * st.y, gg.z, bb.z);
            z.w = fmaf((z.w - st.x) * st.y, gg.w, bb.w);
            out4[i] = z;
        }
    };

    // -------------------- pipelined persistent loop --------------------------
    const int stride = gridDim.x;
    phase0(blockIdx.x, 0);
    __syncthreads();

    int last_t = blockIdx.x;
    int i = 0;
    for (int t = blockIdx.x; t < num_tiles; t += stride, i++) {
        const int buf = i & 1;
        gemm_epi(t, buf);                      // tensor-heavy (writes z, red)
        const int tn = t + stride;
        if (tn < num_tiles) phase0(tn, buf ^ 1);   // fma/MUFU-heavy
        if (i > 0) pass2(t - stride);              // memory-heavy
        __syncthreads();                            // red complete everywhere
        {   // per-row stats for tile t
            float s = 0.f, q = 0.f;
#pragma unroll
            for (int k = 0; k < 16; k++) {
                float2 p = red2[tid * 17 + k];
                s += p.x;
                q += p.y;
            }
            float mu = s * (1.0f / 256.0f);
            float var = fmaxf(q * (1.0f / 256.0f) - mu * mu, 0.0f);
            stat2[tid] = make_float2(mu, rsqrtf(var + 1e-5f));
        }
        __syncthreads();                            // stat2 ready
        last_t = t;
    }
    pass2(last_t);
}

// ---------------------------------------------------------------------------
extern "C" void kernel_launch(void* const* d_in, const int* in_sizes, int n_in,
                              void* d_out, int out_size) {
    const int* read_count  = (const int*)d_in[0];
    const int* write_count = (const int*)d_in[1];
    const int* fault_count = (const int*)d_in[2];
    const int* cow_count   = (const int*)d_in[3];
    const int* recency     = (const int*)d_in[4];
    const float* volatility  = (const float*)d_in[5];
    const float* pressure    = (const float*)d_in[6];
    const float* count_emb   = (const float*)d_in[7];
    const float* recency_emb = (const float*)d_in[8];
    const float* p_w1 = (const float*)d_in[9];
    const float* p_b1 = (const float*)d_in[10];
    const float* p_w2 = (const float*)d_in[11];
    const float* p_b2 = (const float*)d_in[12];
    const float* v_w1 = (const float*)d_in[13];
    const float* v_b1 = (const float*)d_in[14];
    const float* v_w2 = (const float*)d_in[15];
    const float* v_b2 = (const float*)d_in[16];
    const float* f_wh = (const float*)d_in[17];
    const float* f_bh = (const float*)d_in[18];
    const float* f_wg = (const float*)d_in[19];
    const float* f_bg = (const float*)d_in[20];
    const float* ln_g = (const float*)d_in[21];
    const float* ln_b = (const float*)d_in[22];
    float* out = (float*)d_out;

    const int B = in_sizes[0];
    const int num_tiles = B / ROWS_PER_CTA;  // 1024

    int dev = 0, sms = 148;
    cudaGetDevice(&dev);
    cudaDeviceGetAttribute(&sms, cudaDevAttrMultiProcessorCount, dev);
    int grid = num_tiles < sms ? num_tiles : sms;

    quant_prep_kernel<<<4, 512>>>(v_w1, v_w2, p_w1, p_w2);

    cudaFuncSetAttribute(encoder_hmma_kernel,
                         cudaFuncAttributeMaxDynamicSharedMemorySize, SMEM_BYTES);
    encoder_hmma_kernel<<<grid, THREADS, SMEM_BYTES>>>(
        read_count, write_count, fault_count, cow_count, recency,
        volatility, pressure, count_emb, recency_emb,
        p_b1, p_b2, v_b1, v_b2,
        f_wh, f_bh, f_wg, f_bg, ln_g, ln_b, out, num_tiles);
}

// round 7
// speedup vs baseline: 1.2466x; 1.2466x over previous
#include <cuda_runtime.h>
#include <cuda_fp16.h>
#include <cstdint>

// ===========================================================================
// BitNetSummaryEncoder — HMMA, register-resident W (hi+lo), fp16 A,
// smem-staged z (no gmem round trip for layernorm).
//   16 warps; warp w owns output cols [16w,16w+16) (h and g).
//   Tile = 512 rows (phase0); GEMM+LN in 4 subtiles of 128 rows via zbuf smem.
//   2-term split:  A_fp16 * Whi + A_fp16 * Wlo
// ===========================================================================

#define THREADS       512
#define ROWS_PER_CTA  512
#define SUB_ROWS      128
#define ZSTRIDE       260   // floats per zbuf row (4-float aligned, conflict-light)

__device__ float d_q[848];    // quantized ternary weights

// ---------------- smem layout (bytes) --------------------------------------
// init:  [0,131072) = W hi | W lo (frag load only, then dead)
// main:  [0,65536)  = A (512 rows x 128B fp16)
//        [65536, 65536+133120) = zbuf (128 x 260 floats)
#define SM_A    0u
#define SM_WH   0u
#define SM_WL   65536u
#define SM_Z    65536u
#define SM_RED  198656u       // 128 rows x 17 float2 = 17408
#define SM_STAT 216064u       // 128 x float2 = 1024
#define SM_PAR  217088u       // params (float offsets below)
#define P_CEMB  0
#define P_REMB  320
#define P_Q     640
#define P_SB    1488
#define P_LNG   1552
#define P_LNB   1808
#define P_END   2064
#define SMEM_BYTES (SM_PAR + P_END * 4)   // 225344

// ---------------- PTX helpers -----------------------------------------------
__device__ __forceinline__ uint32_t smem_u32(const void* p) {
    uint32_t a;
    asm("{ .reg .u64 t; cvta.to.shared.u64 t, %1; cvt.u32.u64 %0, t; }"
        : "=r"(a) : "l"(p));
    return a;
}
__device__ __forceinline__ void ldsm_x4(uint32_t* r, uint32_t addr) {
    asm volatile("ldmatrix.sync.aligned.m8n8.x4.shared.b16 {%0,%1,%2,%3}, [%4];"
                 : "=r"(r[0]), "=r"(r[1]), "=r"(r[2]), "=r"(r[3]) : "r"(addr));
}
__device__ __forceinline__ void ldsm_x4t(uint32_t* r, uint32_t addr) {
    asm volatile("ldmatrix.sync.aligned.m8n8.x4.trans.shared.b16 {%0,%1,%2,%3}, [%4];"
                 : "=r"(r[0]), "=r"(r[1]), "=r"(r[2]), "=r"(r[3]) : "r"(addr));
}
__device__ __forceinline__ void mma16816(float* d, const uint32_t* a,
                                         const uint32_t* b) {
    asm volatile(
        "mma.sync.aligned.m16n8k16.row.col.f32.f16.f16.f32 "
        "{%0,%1,%2,%3}, {%4,%5,%6,%7}, {%8,%9}, {%0,%1,%2,%3};"
        : "+f"(d[0]), "+f"(d[1]), "+f"(d[2]), "+f"(d[3])
        : "r"(a[0]), "r"(a[1]), "r"(a[2]), "r"(a[3]), "r"(b[0]), "r"(b[1]));
}
__device__ __forceinline__ float gelu_exact(float x) {
    return 0.5f * x * (1.0f + erff(x * 0.7071067811865476f));
}
__device__ __forceinline__ uint32_t pack2h(float a, float b) {
    __half h0 = __float2half_rn(a);
    __half h1 = __float2half_rn(b);
    return (uint32_t)__half_as_ushort(h0) | ((uint32_t)__half_as_ushort(h1) << 16);
}

// ---------------------------------------------------------------------------
__global__ void quant_prep_kernel(const float* __restrict__ vw1,
                                  const float* __restrict__ vw2,
                                  const float* __restrict__ pw1,
                                  const float* __restrict__ pw2) {
    __shared__ float red[512];
    const float* W; int n; float* out;
    switch (blockIdx.x) {
        case 0:  W = vw1; n = 32;  out = d_q;       break;
        case 1:  W = vw2; n = 48;  out = d_q + 32;  break;
        case 2:  W = pw1; n = 288; out = d_q + 80;  break;
        default: W = pw2; n = 480; out = d_q + 368; break;
    }
    int t = threadIdx.x;
    red[t] = (t < n) ? fabsf(W[t]) : 0.0f;
    __syncthreads();
#pragma unroll
    for (int s = 256; s > 0; s >>= 1) {
        if (t < s) red[t] += red[t + s];
        __syncthreads();
    }
    float scale = red[0] / (float)n;
    if (t < n) {
        float q = rintf(W[t] / (scale + 1e-5f));
        q = fminf(fmaxf(q, -1.0f), 1.0f);
        out[t] = q * scale;
    }
}

// ---------------------------------------------------------------------------
__global__ void __launch_bounds__(THREADS, 1)
encoder_hmma_kernel(const int* __restrict__ read_count,
                    const int* __restrict__ write_count,
                    const int* __restrict__ fault_count,
                    const int* __restrict__ cow_count,
                    const int* __restrict__ recency,
                    const float* __restrict__ volatility,
                    const float* __restrict__ pressure,
                    const float* __restrict__ count_emb,
                    const float* __restrict__ recency_emb,
                    const float* __restrict__ p_b1,
                    const float* __restrict__ p_b2,
                    const float* __restrict__ v_b1,
                    const float* __restrict__ v_b2,
                    const float* __restrict__ f_wh,
                    const float* __restrict__ f_bh,
                    const float* __restrict__ f_wg,
                    const float* __restrict__ f_bg,
                    const float* __restrict__ ln_g,
                    const float* __restrict__ ln_b,
                    float* __restrict__ out,
                    int num_tiles) {
    extern __shared__ char smraw[];
    float* spar = (float*)(smraw + SM_PAR);
    const uint32_t sbase = smem_u32(smraw);
    const int tid = threadIdx.x;
    const int w   = tid >> 5;          // 0..15
    const int lid = tid & 31;

    // ---- build W hi/lo in smem (k-major, 1024B rows, 16B-chunk swizzle) ----
    for (int i = tid; i < 512 * 64; i += THREADS) {
        int n = i >> 6, k = i & 63;
        float wv = 0.0f;
        if (k < 51)       wv = (n < 256) ? f_wh[n * 51 + k] : f_wg[(n - 256) * 51 + k];
        else if (k == 51) wv = (n < 256) ? f_bh[n] : f_bg[n - 256];
        __half hi = __float2half_rn(wv);
        __half lo = __float2half_rn(wv - __half2float(hi));
        uint32_t off = (uint32_t)k * 1024u + ((((uint32_t)n >> 3) ^ ((uint32_t)k & 7)) << 4)
                       + (((uint32_t)n & 7) << 1);
        *(__half*)(smraw + SM_WH + off) = hi;
        *(__half*)(smraw + SM_WL + off) = lo;
    }
    for (int i = tid; i < 320; i += THREADS) {
        spar[P_CEMB + i] = count_emb[i];
        spar[P_REMB + i] = recency_emb[i];
    }
    for (int i = tid; i < 848; i += THREADS) spar[P_Q + i] = d_q[i];
    if (tid < 8)  spar[P_SB + tid]      = v_b1[tid];
    if (tid < 6)  spar[P_SB + 8 + tid]  = v_b2[tid];
    if (tid < 24) spar[P_SB + 16 + tid] = p_b1[tid];
    if (tid < 20) spar[P_SB + 40 + tid] = p_b2[tid];
    if (tid < 256) { spar[P_LNG + tid] = ln_g[tid]; spar[P_LNB + tid] = ln_b[tid]; }
    __syncthreads();

    const float* s_q  = spar + P_Q;
    const float* s_sb = spar + P_SB;
    float*  zbuf  = (float*)(smraw + SM_Z);
    float2* red2  = (float2*)(smraw + SM_RED);
    float2* stat2 = (float2*)(smraw + SM_STAT);

    const int grp = lid >> 3, li = lid & 7;
    const int r0  = lid >> 2;           // 0..7
    const int cql = (lid & 3) << 1;     // 0,2,4,6

    // ---- register-resident W fragments (once): hi and lo terms -------------
    // c 0..1: h chunks (cols 16w..16w+16); c 2..3: g chunks (+256)
    uint32_t Bhi[4][8], Blo[4][8];
#pragma unroll
    for (int c = 0; c < 2; c++) {
        const int chh = w * 2 + c;
        const int chg = 32 + w * 2 + c;
#pragma unroll
        for (int kh = 0; kh < 2; kh++) {
            int krow = kh * 32 + grp * 8 + li;
            uint32_t rowoff = (uint32_t)krow * 1024u;
            uint32_t swh = (((uint32_t)(chh ^ (krow & 7))) << 4);
            uint32_t swg = (((uint32_t)(chg ^ (krow & 7))) << 4);
            ldsm_x4t(&Bhi[c][kh * 4],     sbase + SM_WH + rowoff + swh);
            ldsm_x4t(&Blo[c][kh * 4],     sbase + SM_WL + rowoff + swh);
            ldsm_x4t(&Bhi[2 + c][kh * 4], sbase + SM_WH + rowoff + swg);
            ldsm_x4t(&Blo[2 + c][kh * 4], sbase + SM_WL + rowoff + swg);
        }
    }
    __syncthreads();   // W frags in regs; smem now A + zbuf

    // -------------------- persistent tile loop ------------------------------
    for (int t = blockIdx.x; t < num_tiles; t += gridDim.x) {
        const size_t rowbase = (size_t)t * ROWS_PER_CTA;

        // ---- phase 0: scalar front-end, one row per thread -> A smem -------
        {
            const size_t myrow = rowbase + (size_t)tid;
            const uint32_t abase = (uint32_t)tid * 128u;
            float v8[8];
            auto store_chunk = [&](int j, const float* v) {
                uint32_t hw[4];
#pragma unroll
                for (int q = 0; q < 4; q++) hw[q] = pack2h(v[2 * q], v[2 * q + 1]);
                uint32_t off = abase + (((uint32_t)(j ^ (tid & 7))) << 4);
                *(uint4*)(smraw + SM_A + off) = make_uint4(hw[0], hw[1], hw[2], hw[3]);
            };
            const int rc = read_count[myrow], wc = write_count[myrow];
            const int fc = fault_count[myrow], cc = cow_count[myrow];
            const int rr = recency[myrow];
#pragma unroll
            for (int d = 0; d < 5; d++) v8[d] = spar[P_CEMB + rc * 5 + d];
#pragma unroll
            for (int d = 0; d < 3; d++) v8[5 + d] = spar[P_CEMB + wc * 5 + d];
            store_chunk(0, v8);
            v8[0] = spar[P_CEMB + wc * 5 + 3];
            v8[1] = spar[P_CEMB + wc * 5 + 4];
#pragma unroll
            for (int d = 0; d < 5; d++) v8[2 + d] = spar[P_CEMB + fc * 5 + d];
            v8[7] = spar[P_CEMB + cc * 5 + 0];
            store_chunk(1, v8);
#pragma unroll
            for (int d = 0; d < 4; d++) v8[d] = spar[P_CEMB + cc * 5 + 1 + d];
#pragma unroll
            for (int d = 0; d < 4; d++) v8[4 + d] = spar[P_REMB + rr * 5 + d];
            store_chunk(2, v8);

            float4 v4 = ((const float4*)volatility)[myrow];
            float va[4] = {v4.x, v4.y, v4.z, v4.w};
            float v1[8];
#pragma unroll
            for (int j = 0; j < 8; j++) {
                float a = s_sb[j];
#pragma unroll
                for (int i = 0; i < 4; i++) a = fmaf(s_q[j * 4 + i], va[i], a);
                v1[j] = gelu_exact(a);
            }
            float pv[6];
#pragma unroll
            for (int j = 0; j < 6; j++) {
                float a = s_sb[8 + j];
#pragma unroll
                for (int i = 0; i < 8; i++) a = fmaf(s_q[32 + j * 8 + i], v1[i], a);
                pv[j] = a;
            }
            float4 pA = ((const float4*)pressure)[myrow * 3 + 0];
            float4 pB = ((const float4*)pressure)[myrow * 3 + 1];
            float4 pC = ((const float4*)pressure)[myrow * 3 + 2];
            float pr[12] = {pA.x, pA.y, pA.z, pA.w, pB.x, pB.y, pB.z, pB.w,
                            pC.x, pC.y, pC.z, pC.w};
            float p1[24];
#pragma unroll
            for (int j = 0; j < 24; j++) {
                float a = s_sb[16 + j];
#pragma unroll
                for (int i = 0; i < 12; i++) a = fmaf(s_q[80 + j * 12 + i], pr[i], a);
                p1[j] = gelu_exact(a);
            }
            auto pp = [&](int j) {
                float a = s_sb[40 + j];
#pragma unroll
                for (int i = 0; i < 24; i++) a = fmaf(s_q[368 + j * 24 + i], p1[i], a);
                return a;
            };
            v8[0] = spar[P_REMB + rr * 5 + 4];
#pragma unroll
            for (int d = 0; d < 6; d++) v8[1 + d] = pv[d];
            v8[7] = pp(0);
            store_chunk(3, v8);
#pragma unroll
            for (int d = 0; d < 8; d++) v8[d] = pp(1 + d);
            store_chunk(4, v8);
#pragma unroll
            for (int d = 0; d < 8; d++) v8[d] = pp(9 + d);
            store_chunk(5, v8);
            v8[0] = pp(17); v8[1] = pp(18); v8[2] = pp(19);
            v8[3] = 1.0f; v8[4] = 0.f; v8[5] = 0.f; v8[6] = 0.f; v8[7] = 0.f;
            store_chunk(6, v8);
#pragma unroll
            for (int d = 0; d < 8; d++) v8[d] = 0.f;
            store_chunk(7, v8);
        }
        __syncthreads();   // A ready

        // ---- 4 subtiles of 128 rows: GEMM -> zbuf -> stats -> LN store -----
#pragma unroll 1
        for (int sub = 0; sub < 4; sub++) {
            // GEMM (8 m-tiles of 16 rows)
#pragma unroll 1
            for (int mt = 0; mt < 8; mt++) {
                float acc[4][4];
#pragma unroll
                for (int c = 0; c < 4; c++)
#pragma unroll
                    for (int i = 0; i < 4; i++) acc[c][i] = 0.0f;

                const int rloc = sub * SUB_ROWS + mt * 16 + ((grp & 1) << 3) + li;
                const uint32_t roff = (uint32_t)rloc * 128u;
#pragma unroll
                for (int ks = 0; ks < 4; ks++) {
                    uint32_t A[4];
                    const int ch = 2 * ks + (grp >> 1);
                    const uint32_t off = roff + (((uint32_t)(ch ^ (rloc & 7))) << 4);
                    ldsm_x4(A, sbase + SM_A + off);
#pragma unroll
                    for (int c = 0; c < 4; c++) {
                        mma16816(acc[c], A, &Bhi[c][2 * ks]);
                        mma16816(acc[c], A, &Blo[c][2 * ks]);
                    }
                }
                // z = h*sigmoid(g) -> zbuf(smem), partial stats -> red2
                float s0 = 0.f, q0 = 0.f, s8 = 0.f, q8 = 0.f;
                const int zr = mt * 16 + r0;
#pragma unroll
                for (int c = 0; c < 2; c++) {
                    float z0 = acc[c][0] / (1.0f + __expf(-acc[2 + c][0]));
                    float z1 = acc[c][1] / (1.0f + __expf(-acc[2 + c][1]));
                    float z2 = acc[c][2] / (1.0f + __expf(-acc[2 + c][2]));
                    float z3 = acc[c][3] / (1.0f + __expf(-acc[2 + c][3]));
                    const int col = w * 16 + c * 8 + cql;
                    *(float2*)(zbuf + zr * ZSTRIDE + col)       = make_float2(z0, z1);
                    *(float2*)(zbuf + (zr + 8) * ZSTRIDE + col) = make_float2(z2, z3);
                    s0 += z0 + z1;
                    q0 = fmaf(z0, z0, fmaf(z1, z1, q0));
                    s8 += z2 + z3;
                    q8 = fmaf(z2, z2, fmaf(z3, z3, q8));
                }
                s0 += __shfl_xor_sync(0xffffffffu, s0, 1);
                q0 += __shfl_xor_sync(0xffffffffu, q0, 1);
                s8 += __shfl_xor_sync(0xffffffffu, s8, 1);
                q8 += __shfl_xor_sync(0xffffffffu, q8, 1);
                s0 += __shfl_xor_sync(0xffffffffu, s0, 2);
                q0 += __shfl_xor_sync(0xffffffffu, q0, 2);
                s8 += __shfl_xor_sync(0xffffffffu, s8, 2);
                q8 += __shfl_xor_sync(0xffffffffu, q8, 2);
                if ((lid & 3) == 0) {
                    red2[zr * 17 + w]       = make_float2(s0, q0);
                    red2[(zr + 8) * 17 + w] = make_float2(s8, q8);
                }
            }
            __syncthreads();   // zbuf + red2 ready

            // per-row stats (128 rows)
            if (tid < SUB_ROWS) {
                float s = 0.f, q = 0.f;
#pragma unroll
                for (int k = 0; k < 16; k++) {
                    float2 p = red2[tid * 17 + k];
                    s += p.x;
                    q += p.y;
                }
                float mu = s * (1.0f / 256.0f);
                float var = fmaxf(q * (1.0f / 256.0f) - mu * mu, 0.0f);
                stat2[tid] = make_float2(mu, rsqrtf(var + 1e-5f));
            }
            __syncthreads();   // stats ready

            // normalize from smem, single coalesced gmem write
            {
                const float4* lng4 = (const float4*)(spar + P_LNG);
                const float4* lnb4 = (const float4*)(spar + P_LNB);
                float4* out4 = (float4*)(out + (rowbase + (size_t)sub * SUB_ROWS) * 256);
#pragma unroll 4
                for (int i = tid; i < SUB_ROWS * 64; i += THREADS) {
                    const int r = i >> 6, c4 = i & 63;
                    float4 z = *(const float4*)(zbuf + r * ZSTRIDE + c4 * 4);
                    float2 st = stat2[r];
                    float4 gg = lng4[c4];
                    float4 bb = lnb4[c4];
                    z.x = fmaf((z.x - st.x) * st.y, gg.x, bb.x);
                    z.y = fmaf((z.y - st.x) * st.y, gg.y, bb.y);
                    z.z = fmaf((z.z - st.x) * st.y, gg.z, bb.z);
                    z.w = fmaf((z.w - st.x) * st.y, gg.w, bb.w);
                    out4[(size_t)r * 64 + c4] = z;
                }
            }
            __syncthreads();   // zbuf reusable
        }
    }
}

// ---------------------------------------------------------------------------
extern "C" void kernel_launch(void* const* d_in, const int* in_sizes, int n_in,
                              void* d_out, int out_size) {
    const int* read_count  = (const int*)d_in[0];
    const int* write_count = (const int*)d_in[1];
    const int* fault_count = (const int*)d_in[2];
    const int* cow_count   = (const int*)d_in[3];
    const int* recency     = (const int*)d_in[4];
    const float* volatility  = (const float*)d_in[5];
    const float* pressure    = (const float*)d_in[6];
    const float* count_emb   = (const float*)d_in[7];
    const float* recency_emb = (const float*)d_in[8];
    const float* p_w1 = (const float*)d_in[9];
    const float* p_b1 = (const float*)d_in[10];
    const float* p_w2 = (const float*)d_in[11];
    const float* p_b2 = (const float*)d_in[12];
    const float* v_w1 = (const float*)d_in[13];
    const float* v_b1 = (const float*)d_in[14];
    const float* v_w2 = (const float*)d_in[15];
    const float* v_b2 = (const float*)d_in[16];
    const float* f_wh = (const float*)d_in[17];
    const float* f_bh = (const float*)d_in[18];
    const float* f_wg = (const float*)d_in[19];
    const float* f_bg = (const float*)d_in[20];
    const float* ln_g = (const float*)d_in[21];
    const float* ln_b = (const float*)d_in[22];
    float* out = (float*)d_out;

    const int B = in_sizes[0];
    const int num_tiles = B / ROWS_PER_CTA;  // 1024

    int dev = 0, sms = 148;
    cudaGetDevice(&dev);
    cudaDeviceGetAttribute(&sms, cudaDevAttrMultiProcessorCount, dev);
    int grid = num_tiles < sms ? num_tiles : sms;

    quant_prep_kernel<<<4, 512>>>(v_w1, v_w2, p_w1, p_w2);

    cudaFuncSetAttribute(encoder_hmma_kernel,
                         cudaFuncAttributeMaxDynamicSharedMemorySize, SMEM_BYTES);
    encoder_hmma_kernel<<<grid, THREADS, SMEM_BYTES>>>(
        read_count, write_count, fault_count, cow_count, recency,
        volatility, pressure, count_emb, recency_emb,
        p_b1, p_b2, v_b1, v_b2,
        f_wh, f_bh, f_wg, f_bg, ln_g, ln_b, out, num_tiles);
}

// round 8
// speedup vs baseline: 2.0499x; 1.6443x over previous
#include <cuda_runtime.h>
#include <cuda_fp16.h>
#include <cstdint>

// ===========================================================================
// BitNetSummaryEncoder — HMMA, register-resident W (single fp16), fp16 A,
// smem-staged z (no gmem round trip for layernorm).
//   16 warps; warp w owns output cols [16w,16w+16) (h and g).
//   Tile = 512 rows (phase0); GEMM+LN in 4 subtiles of 128 rows via zbuf smem.
//   1-term:  A_fp16 * W_fp16  (rel_err ~3e-4 < 1e-3 gate)
// ===========================================================================

#define THREADS       512
#define ROWS_PER_CTA  512
#define SUB_ROWS      128
#define ZSTRIDE       260   // floats per zbuf row

__device__ float d_q[848];    // quantized ternary weights

// ---------------- smem layout (bytes) --------------------------------------
// init:  [0,65536) = W fp16 (frag load only, then dead)
// main:  [0,65536)  = A (512 rows x 128B fp16)
//        [65536, 65536+133120) = zbuf (128 x 260 floats)
#define SM_A    0u
#define SM_WH   0u
#define SM_Z    65536u
#define SM_RED  198656u       // 128 rows x 17 float2 = 17408
#define SM_STAT 216064u       // 128 x float2 = 1024
#define SM_PAR  217088u       // params (float offsets below)
#define P_CEMB  0
#define P_REMB  320
#define P_Q     640
#define P_SB    1488
#define P_LNG   1552
#define P_LNB   1808
#define P_END   2064
#define SMEM_BYTES (SM_PAR + P_END * 4)   // 225344

// ---------------- PTX helpers -----------------------------------------------
__device__ __forceinline__ uint32_t smem_u32(const void* p) {
    uint32_t a;
    asm("{ .reg .u64 t; cvta.to.shared.u64 t, %1; cvt.u32.u64 %0, t; }"
        : "=r"(a) : "l"(p));
    return a;
}
__device__ __forceinline__ void ldsm_x4(uint32_t* r, uint32_t addr) {
    asm volatile("ldmatrix.sync.aligned.m8n8.x4.shared.b16 {%0,%1,%2,%3}, [%4];"
                 : "=r"(r[0]), "=r"(r[1]), "=r"(r[2]), "=r"(r[3]) : "r"(addr));
}
__device__ __forceinline__ void ldsm_x4t(uint32_t* r, uint32_t addr) {
    asm volatile("ldmatrix.sync.aligned.m8n8.x4.trans.shared.b16 {%0,%1,%2,%3}, [%4];"
                 : "=r"(r[0]), "=r"(r[1]), "=r"(r[2]), "=r"(r[3]) : "r"(addr));
}
__device__ __forceinline__ void mma16816(float* d, const uint32_t* a,
                                         const uint32_t* b) {
    asm volatile(
        "mma.sync.aligned.m16n8k16.row.col.f32.f16.f16.f32 "
        "{%0,%1,%2,%3}, {%4,%5,%6,%7}, {%8,%9}, {%0,%1,%2,%3};"
        : "+f"(d[0]), "+f"(d[1]), "+f"(d[2]), "+f"(d[3])
        : "r"(a[0]), "r"(a[1]), "r"(a[2]), "r"(a[3]), "r"(b[0]), "r"(b[1]));
}
__device__ __forceinline__ float gelu_exact(float x) {
    return 0.5f * x * (1.0f + erff(x * 0.7071067811865476f));
}
__device__ __forceinline__ uint32_t pack2h(float a, float b) {
    __half h0 = __float2half_rn(a);
    __half h1 = __float2half_rn(b);
    return (uint32_t)__half_as_ushort(h0) | ((uint32_t)__half_as_ushort(h1) << 16);
}
__device__ __forceinline__ float fast_glu(float h, float g) {
    // h * sigmoid(g), approximate reciprocal (error << precision budget)
    return __fdividef(h, 1.0f + __expf(-g));
}

// ---------------------------------------------------------------------------
__global__ void quant_prep_kernel(const float* __restrict__ vw1,
                                  const float* __restrict__ vw2,
                                  const float* __restrict__ pw1,
                                  const float* __restrict__ pw2) {
    __shared__ float red[512];
    const float* W; int n; float* out;
    switch (blockIdx.x) {
        case 0:  W = vw1; n = 32;  out = d_q;       break;
        case 1:  W = vw2; n = 48;  out = d_q + 32;  break;
        case 2:  W = pw1; n = 288; out = d_q + 80;  break;
        default: W = pw2; n = 480; out = d_q + 368; break;
    }
    int t = threadIdx.x;
    red[t] = (t < n) ? fabsf(W[t]) : 0.0f;
    __syncthreads();
#pragma unroll
    for (int s = 256; s > 0; s >>= 1) {
        if (t < s) red[t] += red[t + s];
        __syncthreads();
    }
    float scale = red[0] / (float)n;
    if (t < n) {
        float q = rintf(W[t] / (scale + 1e-5f));
        q = fminf(fmaxf(q, -1.0f), 1.0f);
        out[t] = q * scale;
    }
}

// ---------------------------------------------------------------------------
__global__ void __launch_bounds__(THREADS, 1)
encoder_hmma_kernel(const int* __restrict__ read_count,
                    const int* __restrict__ write_count,
                    const int* __restrict__ fault_count,
                    const int* __restrict__ cow_count,
                    const int* __restrict__ recency,
                    const float* __restrict__ volatility,
                    const float* __restrict__ pressure,
                    const float* __restrict__ count_emb,
                    const float* __restrict__ recency_emb,
                    const float* __restrict__ p_b1,
                    const float* __restrict__ p_b2,
                    const float* __restrict__ v_b1,
                    const float* __restrict__ v_b2,
                    const float* __restrict__ f_wh,
                    const float* __restrict__ f_bh,
                    const float* __restrict__ f_wg,
                    const float* __restrict__ f_bg,
                    const float* __restrict__ ln_g,
                    const float* __restrict__ ln_b,
                    float* __restrict__ out,
                    int num_tiles) {
    extern __shared__ char smraw[];
    float* spar = (float*)(smraw + SM_PAR);
    const uint32_t sbase = smem_u32(smraw);
    const int tid = threadIdx.x;
    const int w   = tid >> 5;          // 0..15
    const int lid = tid & 31;

    // ---- build W fp16 in smem (k-major, 1024B rows, 16B-chunk swizzle) -----
    for (int i = tid; i < 512 * 64; i += THREADS) {
        int n = i >> 6, k = i & 63;
        float wv = 0.0f;
        if (k < 51)       wv = (n < 256) ? f_wh[n * 51 + k] : f_wg[(n - 256) * 51 + k];
        else if (k == 51) wv = (n < 256) ? f_bh[n] : f_bg[n - 256];
        uint32_t off = (uint32_t)k * 1024u + ((((uint32_t)n >> 3) ^ ((uint32_t)k & 7)) << 4)
                       + (((uint32_t)n & 7) << 1);
        *(__half*)(smraw + SM_WH + off) = __float2half_rn(wv);
    }
    for (int i = tid; i < 320; i += THREADS) {
        spar[P_CEMB + i] = count_emb[i];
        spar[P_REMB + i] = recency_emb[i];
    }
    for (int i = tid; i < 848; i += THREADS) spar[P_Q + i] = d_q[i];
    if (tid < 8)  spar[P_SB + tid]      = v_b1[tid];
    if (tid < 6)  spar[P_SB + 8 + tid]  = v_b2[tid];
    if (tid < 24) spar[P_SB + 16 + tid] = p_b1[tid];
    if (tid < 20) spar[P_SB + 40 + tid] = p_b2[tid];
    if (tid < 256) { spar[P_LNG + tid] = ln_g[tid]; spar[P_LNB + tid] = ln_b[tid]; }
    __syncthreads();

    const float* s_q  = spar + P_Q;
    const float* s_sb = spar + P_SB;
    float*  zbuf  = (float*)(smraw + SM_Z);
    float2* red2  = (float2*)(smraw + SM_RED);
    float2* stat2 = (float2*)(smraw + SM_STAT);

    const int grp = lid >> 3, li = lid & 7;
    const int r0  = lid >> 2;           // 0..7
    const int cql = (lid & 3) << 1;     // 0,2,4,6

    // ---- register-resident W fragments (once) -------------------------------
    // c 0..1: h chunks (cols 16w..16w+16); c 2..3: g chunks (+256)
    uint32_t Bf[4][8];
#pragma unroll
    for (int c = 0; c < 2; c++) {
        const int chh = w * 2 + c;
        const int chg = 32 + w * 2 + c;
#pragma unroll
        for (int kh = 0; kh < 2; kh++) {
            int krow = kh * 32 + grp * 8 + li;
            uint32_t rowoff = (uint32_t)krow * 1024u;
            uint32_t swh = (((uint32_t)(chh ^ (krow & 7))) << 4);
            uint32_t swg = (((uint32_t)(chg ^ (krow & 7))) << 4);
            ldsm_x4t(&Bf[c][kh * 4],     sbase + SM_WH + rowoff + swh);
            ldsm_x4t(&Bf[2 + c][kh * 4], sbase + SM_WH + rowoff + swg);
        }
    }
    __syncthreads();   // W frags in regs; smem now A + zbuf

    // -------------------- persistent tile loop ------------------------------
    for (int t = blockIdx.x; t < num_tiles; t += gridDim.x) {
        const size_t rowbase = (size_t)t * ROWS_PER_CTA;

        // ---- phase 0: scalar front-end, one row per thread -> A smem -------
        {
            const size_t myrow = rowbase + (size_t)tid;
            const uint32_t abase = (uint32_t)tid * 128u;
            float v8[8];
            auto store_chunk = [&](int j, const float* v) {
                uint32_t hw[4];
#pragma unroll
                for (int q = 0; q < 4; q++) hw[q] = pack2h(v[2 * q], v[2 * q + 1]);
                uint32_t off = abase + (((uint32_t)(j ^ (tid & 7))) << 4);
                *(uint4*)(smraw + SM_A + off) = make_uint4(hw[0], hw[1], hw[2], hw[3]);
            };
            const int rc = read_count[myrow], wc = write_count[myrow];
            const int fc = fault_count[myrow], cc = cow_count[myrow];
            const int rr = recency[myrow];
#pragma unroll
            for (int d = 0; d < 5; d++) v8[d] = spar[P_CEMB + rc * 5 + d];
#pragma unroll
            for (int d = 0; d < 3; d++) v8[5 + d] = spar[P_CEMB + wc * 5 + d];
            store_chunk(0, v8);
            v8[0] = spar[P_CEMB + wc * 5 + 3];
            v8[1] = spar[P_CEMB + wc * 5 + 4];
#pragma unroll
            for (int d = 0; d < 5; d++) v8[2 + d] = spar[P_CEMB + fc * 5 + d];
            v8[7] = spar[P_CEMB + cc * 5 + 0];
            store_chunk(1, v8);
#pragma unroll
            for (int d = 0; d < 4; d++) v8[d] = spar[P_CEMB + cc * 5 + 1 + d];
#pragma unroll
            for (int d = 0; d < 4; d++) v8[4 + d] = spar[P_REMB + rr * 5 + d];
            store_chunk(2, v8);

            float4 v4 = ((const float4*)volatility)[myrow];
            float va[4] = {v4.x, v4.y, v4.z, v4.w};
            float v1[8];
#pragma unroll
            for (int j = 0; j < 8; j++) {
                float a = s_sb[j];
#pragma unroll
                for (int i = 0; i < 4; i++) a = fmaf(s_q[j * 4 + i], va[i], a);
                v1[j] = gelu_exact(a);
            }
            float pv[6];
#pragma unroll
            for (int j = 0; j < 6; j++) {
                float a = s_sb[8 + j];
#pragma unroll
                for (int i = 0; i < 8; i++) a = fmaf(s_q[32 + j * 8 + i], v1[i], a);
                pv[j] = a;
            }
            float4 pA = ((const float4*)pressure)[myrow * 3 + 0];
            float4 pB = ((const float4*)pressure)[myrow * 3 + 1];
            float4 pC = ((const float4*)pressure)[myrow * 3 + 2];
            float pr[12] = {pA.x, pA.y, pA.z, pA.w, pB.x, pB.y, pB.z, pB.w,
                            pC.x, pC.y, pC.z, pC.w};
            float p1[24];
#pragma unroll
            for (int j = 0; j < 24; j++) {
                float a = s_sb[16 + j];
#pragma unroll
                for (int i = 0; i < 12; i++) a = fmaf(s_q[80 + j * 12 + i], pr[i], a);
                p1[j] = gelu_exact(a);
            }
            auto pp = [&](int j) {
                float a = s_sb[40 + j];
#pragma unroll
                for (int i = 0; i < 24; i++) a = fmaf(s_q[368 + j * 24 + i], p1[i], a);
                return a;
            };
            v8[0] = spar[P_REMB + rr * 5 + 4];
#pragma unroll
            for (int d = 0; d < 6; d++) v8[1 + d] = pv[d];
            v8[7] = pp(0);
            store_chunk(3, v8);
#pragma unroll
            for (int d = 0; d < 8; d++) v8[d] = pp(1 + d);
            store_chunk(4, v8);
#pragma unroll
            for (int d = 0; d < 8; d++) v8[d] = pp(9 + d);
            store_chunk(5, v8);
            v8[0] = pp(17); v8[1] = pp(18); v8[2] = pp(19);
            v8[3] = 1.0f; v8[4] = 0.f; v8[5] = 0.f; v8[6] = 0.f; v8[7] = 0.f;
            store_chunk(6, v8);
#pragma unroll
            for (int d = 0; d < 8; d++) v8[d] = 0.f;
            store_chunk(7, v8);
        }
        __syncthreads();   // A ready

        // ---- 4 subtiles of 128 rows: GEMM -> zbuf -> stats -> LN store -----
#pragma unroll 1
        for (int sub = 0; sub < 4; sub++) {
#pragma unroll 1
            for (int mt = 0; mt < 8; mt++) {
                float acc[4][4];
#pragma unroll
                for (int c = 0; c < 4; c++)
#pragma unroll
                    for (int i = 0; i < 4; i++) acc[c][i] = 0.0f;

                const int rloc = sub * SUB_ROWS + mt * 16 + ((grp & 1) << 3) + li;
                const uint32_t roff = (uint32_t)rloc * 128u;
#pragma unroll
                for (int ks = 0; ks < 4; ks++) {
                    uint32_t A[4];
                    const int ch = 2 * ks + (grp >> 1);
                    const uint32_t off = roff + (((uint32_t)(ch ^ (rloc & 7))) << 4);
                    ldsm_x4(A, sbase + SM_A + off);
#pragma unroll
                    for (int c = 0; c < 4; c++)
                        mma16816(acc[c], A, &Bf[c][2 * ks]);
                }
                // z = h*sigmoid(g) -> zbuf(smem), partial stats -> red2
                float s0 = 0.f, q0 = 0.f, s8 = 0.f, q8 = 0.f;
                const int zr = mt * 16 + r0;
#pragma unroll
                for (int c = 0; c < 2; c++) {
                    float z0 = fast_glu(acc[c][0], acc[2 + c][0]);
                    float z1 = fast_glu(acc[c][1], acc[2 + c][1]);
                    float z2 = fast_glu(acc[c][2], acc[2 + c][2]);
                    float z3 = fast_glu(acc[c][3], acc[2 + c][3]);
                    const int col = w * 16 + c * 8 + cql;
                    *(float2*)(zbuf + zr * ZSTRIDE + col)       = make_float2(z0, z1);
                    *(float2*)(zbuf + (zr + 8) * ZSTRIDE + col) = make_float2(z2, z3);
                    s0 += z0 + z1;
                    q0 = fmaf(z0, z0, fmaf(z1, z1, q0));
                    s8 += z2 + z3;
                    q8 = fmaf(z2, z2, fmaf(z3, z3, q8));
                }
                s0 += __shfl_xor_sync(0xffffffffu, s0, 1);
                q0 += __shfl_xor_sync(0xffffffffu, q0, 1);
                s8 += __shfl_xor_sync(0xffffffffu, s8, 1);
                q8 += __shfl_xor_sync(0xffffffffu, q8, 1);
                s0 += __shfl_xor_sync(0xffffffffu, s0, 2);
                q0 += __shfl_xor_sync(0xffffffffu, q0, 2);
                s8 += __shfl_xor_sync(0xffffffffu, s8, 2);
                q8 += __shfl_xor_sync(0xffffffffu, q8, 2);
                if ((lid & 3) == 0) {
                    red2[zr * 17 + w]       = make_float2(s0, q0);
                    red2[(zr + 8) * 17 + w] = make_float2(s8, q8);
                }
            }
            __syncthreads();   // zbuf + red2 ready

            if (tid < SUB_ROWS) {
                float s = 0.f, q = 0.f;
#pragma unroll
                for (int k = 0; k < 16; k++) {
                    float2 p = red2[tid * 17 + k];
                    s += p.x;
                    q += p.y;
                }
                float mu = s * (1.0f / 256.0f);
                float var = fmaxf(q * (1.0f / 256.0f) - mu * mu, 0.0f);
                stat2[tid] = make_float2(mu, rsqrtf(var + 1e-5f));
            }
            __syncthreads();   // stats ready

            {
                const float4* lng4 = (const float4*)(spar + P_LNG);
                const float4* lnb4 = (const float4*)(spar + P_LNB);
                float4* out4 = (float4*)(out + (rowbase + (size_t)sub * SUB_ROWS) * 256);
#pragma unroll 4
                for (int i = tid; i < SUB_ROWS * 64; i += THREADS) {
                    const int r = i >> 6, c4 = i & 63;
                    float4 z = *(const float4*)(zbuf + r * ZSTRIDE + c4 * 4);
                    float2 st = stat2[r];
                    float4 gg = lng4[c4];
                    float4 bb = lnb4[c4];
                    z.x = fmaf((z.x - st.x) * st.y, gg.x, bb.x);
                    z.y = fmaf((z.y - st.x) * st.y, gg.y, bb.y);
                    z.z = fmaf((z.z - st.x) * st.y, gg.z, bb.z);
                    z.w = fmaf((z.w - st.x) * st.y, gg.w, bb.w);
                    out4[(size_t)r * 64 + c4] = z;
                }
            }
            __syncthreads();   // zbuf reusable
        }
    }
}

// ---------------------------------------------------------------------------
extern "C" void kernel_launch(void* const* d_in, const int* in_sizes, int n_in,
                              void* d_out, int out_size) {
    const int* read_count  = (const int*)d_in[0];
    const int* write_count = (const int*)d_in[1];
    const int* fault_count = (const int*)d_in[2];
    const int* cow_count   = (const int*)d_in[3];
    const int* recency     = (const int*)d_in[4];
    const float* volatility  = (const float*)d_in[5];
    const float* pressure    = (const float*)d_in[6];
    const float* count_emb   = (const float*)d_in[7];
    const float* recency_emb = (const float*)d_in[8];
    const float* p_w1 = (const float*)d_in[9];
    const float* p_b1 = (const float*)d_in[10];
    const float* p_w2 = (const float*)d_in[11];
    const float* p_b2 = (const float*)d_in[12];
    const float* v_w1 = (const float*)d_in[13];
    const float* v_b1 = (const float*)d_in[14];
    const float* v_w2 = (const float*)d_in[15];
    const float* v_b2 = (const float*)d_in[16];
    const float* f_wh = (const float*)d_in[17];
    const float* f_bh = (const float*)d_in[18];
    const float* f_wg = (const float*)d_in[19];
    const float* f_bg = (const float*)d_in[20];
    const float* ln_g = (const float*)d_in[21];
    const float* ln_b = (const float*)d_in[22];
    float* out = (float*)d_out;

    const int B = in_sizes[0];
    const int num_tiles = B / ROWS_PER_CTA;  // 1024

    int dev = 0, sms = 148;
    cudaGetDevice(&dev);
    cudaDeviceGetAttribute(&sms, cudaDevAttrMultiProcessorCount, dev);
    int grid = num_tiles < sms ? num_tiles : sms;

    quant_prep_kernel<<<4, 512>>>(v_w1, v_w2, p_w1, p_w2);

    cudaFuncSetAttribute(encoder_hmma_kernel,
                         cudaFuncAttributeMaxDynamicSharedMemorySize, SMEM_BYTES);
    encoder_hmma_kernel<<<grid, THREADS, SMEM_BYTES>>>(
        read_count, write_count, fault_count, cow_count, recency,
        volatility, pressure, count_emb, recency_emb,
        p_b1, p_b2, v_b1, v_b2,
        f_wh, f_bh, f_wg, f_bg, ln_g, ln_b, out, num_tiles);
}